// round 1
// baseline (speedup 1.0000x reference)
#include <cuda_runtime.h>
#include <cuda_bf16.h>
#include <math.h>

// Problem: miniBatchOT. B=4096 rows, concat dim 1024.
// cost[i][j] = max(0, 0.5*||f_i - z_j||^2), f=[feature|text[gt]], z=[zero_feature|zero_text[gt]]
// Sinkhorn (eps=0.05, 50 iters, log-domain) -> pi ; out = sum(pi*cost)
//
// All Sinkhorn math in base-2: lu2 = log2(u), lv2 = log2(v), mK2 = -cost*log2(e)/eps.

#define NB 4096
#define DD 1024
#define NEGK2 (-28.853900817779268f)   /* -log2(e)/eps */
#define TH    96.0f                    /* skip threshold (log2 units) */
#define ETH   60.0f                    /* loss skip threshold */

static __device__ __align__(16) float g_f[NB * DD];
static __device__ __align__(16) float g_z[NB * DD];
static __device__ __align__(16) float g_x2[NB];
static __device__ __align__(16) float g_y2[NB];
static __device__ __align__(16) float g_cost[(size_t)NB * NB];
static __device__ __align__(16) float g_lu[NB];
static __device__ __align__(16) float g_lv[NB];
static __device__ float g_rowmin[NB];
static __device__ int   g_rowarg[NB];
static __device__ float g_colmin[NB];
static __device__ int   g_colarg[NB];

// ---------------------------------------------------------------- helpers
__device__ __forceinline__ void lse_update(float& m, float& s, float x) {
    // online log2-sum-exp2 accumulate of one element
    if (x <= m) {
        s += exp2f(x - m);
    } else {
        s = fmaf(s, exp2f(m - x), 1.0f);
        m = x;
    }
}

__device__ __forceinline__ void lse_merge(float& m, float& s, float mo, float so) {
    float M = fmaxf(m, mo);
    s = s * exp2f(m - M) + so * exp2f(mo - M);
    m = M;
}

// ---------------------------------------------------------------- build f,z
__global__ void build_fz(const float* __restrict__ feat,
                         const float* __restrict__ zfeat,
                         const float* __restrict__ text,
                         const float* __restrict__ ztext,
                         const int*   __restrict__ gt,
                         float* __restrict__ out)
{
    int idx = blockIdx.x * blockDim.x + threadIdx.x;
    if (idx == 0) out[0] = 0.0f;          // zero the scalar output each replay
    if (idx >= NB * DD) return;
    int i = idx >> 10;
    int d = idx & 1023;
    int g = gt[i];
    float fv, zv;
    if (d < 512) {
        fv = feat[i * 512 + d];
        zv = zfeat[i * 512 + d];
    } else {
        int dd = d - 512;
        fv = text[g * 512 + dd];
        zv = ztext[g * 512 + dd];
    }
    g_f[idx] = fv;
    g_z[idx] = zv;
}

// ---------------------------------------------------------------- row norms + dual init
__global__ void sumsq_init()
{
    int warp = threadIdx.x >> 5, lane = threadIdx.x & 31;
    int i = blockIdx.x * 8 + warp;
    const float4* f4 = reinterpret_cast<const float4*>(g_f + (size_t)i * DD);
    const float4* z4 = reinterpret_cast<const float4*>(g_z + (size_t)i * DD);
    float sx = 0.f, sz = 0.f;
    for (int j = lane; j < DD / 4; j += 32) {
        float4 a = f4[j];
        float4 b = z4[j];
        sx += a.x * a.x + a.y * a.y + a.z * a.z + a.w * a.w;
        sz += b.x * b.x + b.y * b.y + b.z * b.z + b.w * b.w;
    }
#pragma unroll
    for (int off = 16; off; off >>= 1) {
        sx += __shfl_xor_sync(0xffffffffu, sx, off);
        sz += __shfl_xor_sync(0xffffffffu, sz, off);
    }
    if (lane == 0) {
        g_x2[i] = sx;
        g_y2[i] = sz;
        g_lu[i] = 0.f;
        g_lv[i] = 0.f;
    }
}

// ---------------------------------------------------------------- cost GEMM
// cost = max(0, 0.5*x2_i + 0.5*y2_j - f_i . z_j)   (128x128 tile, 8x8/thread)
__global__ __launch_bounds__(256) void gemm_cost()
{
    __shared__ float As[8][128];
    __shared__ float Bs[8][128];
    const int tid  = threadIdx.x;
    const int lrow = tid >> 1;
    const int lk   = (tid & 1) * 4;
    const int tx   = tid & 15;
    const int ty   = tid >> 4;
    const int rowBase = blockIdx.y * 128;
    const int colBase = blockIdx.x * 128;
    const float* Ap = g_f + (size_t)(rowBase + lrow) * DD + lk;
    const float* Bp = g_z + (size_t)(colBase + lrow) * DD + lk;

    float acc[8][8];
#pragma unroll
    for (int a = 0; a < 8; a++)
#pragma unroll
        for (int b = 0; b < 8; b++) acc[a][b] = 0.f;

    for (int k0 = 0; k0 < DD; k0 += 8) {
        float4 a4 = *reinterpret_cast<const float4*>(Ap + k0);
        float4 b4 = *reinterpret_cast<const float4*>(Bp + k0);
        __syncthreads();
        As[lk + 0][lrow] = a4.x; As[lk + 1][lrow] = a4.y;
        As[lk + 2][lrow] = a4.z; As[lk + 3][lrow] = a4.w;
        Bs[lk + 0][lrow] = b4.x; Bs[lk + 1][lrow] = b4.y;
        Bs[lk + 2][lrow] = b4.z; Bs[lk + 3][lrow] = b4.w;
        __syncthreads();
#pragma unroll
        for (int k = 0; k < 8; k++) {
            float a[8], b[8];
            *reinterpret_cast<float4*>(a)     = *reinterpret_cast<const float4*>(&As[k][ty * 8]);
            *reinterpret_cast<float4*>(a + 4) = *reinterpret_cast<const float4*>(&As[k][ty * 8 + 4]);
            *reinterpret_cast<float4*>(b)     = *reinterpret_cast<const float4*>(&Bs[k][tx * 8]);
            *reinterpret_cast<float4*>(b + 4) = *reinterpret_cast<const float4*>(&Bs[k][tx * 8 + 4]);
#pragma unroll
            for (int ii = 0; ii < 8; ii++)
#pragma unroll
                for (int jj = 0; jj < 8; jj++)
                    acc[ii][jj] = fmaf(a[ii], b[jj], acc[ii][jj]);
        }
    }

    float hy[8];
#pragma unroll
    for (int jj = 0; jj < 8; jj++) hy[jj] = 0.5f * g_y2[colBase + tx * 8 + jj];

#pragma unroll
    for (int ii = 0; ii < 8; ii++) {
        int i = rowBase + ty * 8 + ii;
        float hx = 0.5f * g_x2[i];
        float tmp[8];
#pragma unroll
        for (int jj = 0; jj < 8; jj++)
            tmp[jj] = fmaxf(0.f, hx + hy[jj] - acc[ii][jj]);
        float* orow = g_cost + (size_t)i * NB + colBase + tx * 8;
        *reinterpret_cast<float4*>(orow)     = *reinterpret_cast<const float4*>(tmp);
        *reinterpret_cast<float4*>(orow + 4) = *reinterpret_cast<const float4*>(tmp + 4);
    }
}

// ---------------------------------------------------------------- row / col argmin (seeds)
__global__ void rowmin_kernel()
{
    int warp = threadIdx.x >> 5, lane = threadIdx.x & 31;
    int i = blockIdx.x * 8 + warp;
    const float4* crow = reinterpret_cast<const float4*>(g_cost + (size_t)i * NB);
    float mn = 3.4e38f;
    int arg = 0;
    for (int j4 = lane; j4 < NB / 4; j4 += 32) {
        float4 c = crow[j4];
        int j = j4 * 4;
        if (c.x < mn) { mn = c.x; arg = j; }
        if (c.y < mn) { mn = c.y; arg = j + 1; }
        if (c.z < mn) { mn = c.z; arg = j + 2; }
        if (c.w < mn) { mn = c.w; arg = j + 3; }
    }
#pragma unroll
    for (int off = 16; off; off >>= 1) {
        float mo = __shfl_xor_sync(0xffffffffu, mn, off);
        int   ao = __shfl_xor_sync(0xffffffffu, arg, off);
        if (mo < mn) { mn = mo; arg = ao; }
    }
    if (lane == 0) { g_rowmin[i] = mn; g_rowarg[i] = arg; }
}

__global__ void colmin_kernel()
{
    __shared__ float smn[8][33];
    __shared__ int   sar[8][33];
    int warp = threadIdx.x >> 5, lane = threadIdx.x & 31;
    int c = blockIdx.x * 32 + lane;
    float mn = 3.4e38f;
    int arg = 0;
    int rbase = warp * 512;
    for (int rr = 0; rr < 512; rr++) {
        float v = g_cost[(size_t)(rbase + rr) * NB + c];
        if (v < mn) { mn = v; arg = rbase + rr; }
    }
    smn[warp][lane] = mn;
    sar[warp][lane] = arg;
    __syncthreads();
    if (warp == 0) {
#pragma unroll
        for (int w = 1; w < 8; w++) {
            if (smn[w][lane] < mn) { mn = smn[w][lane]; arg = sar[w][lane]; }
        }
        g_colmin[c] = mn;
        g_colarg[c] = arg;
    }
}

// ---------------------------------------------------------------- Sinkhorn passes
// Row pass: lu2_i = -12 - log2sum_j 2^(mK2_ij + lv2_j). Warp per row, chunk-skip.
__global__ void row_pass()
{
    int warp = threadIdx.x >> 5, lane = threadIdx.x & 31;
    int i = blockIdx.x * 8 + warp;
    float m_init = fmaf(NEGK2, g_rowmin[i], g_lv[g_rowarg[i]]);
    float thresh = m_init - TH;
    float m = m_init, s = 0.f;
    const float4* crow = reinterpret_cast<const float4*>(g_cost + (size_t)i * NB);
    const float4* lv4  = reinterpret_cast<const float4*>(g_lv);
#pragma unroll 4
    for (int step = 0; step < NB / 128; step++) {
        int j4 = step * 32 + lane;
        float4 c = crow[j4];
        float4 v = lv4[j4];
        float x0 = fmaf(NEGK2, c.x, v.x);
        float x1 = fmaf(NEGK2, c.y, v.y);
        float x2 = fmaf(NEGK2, c.z, v.z);
        float x3 = fmaf(NEGK2, c.w, v.w);
        float mm = fmaxf(fmaxf(x0, x1), fmaxf(x2, x3));
        if (__any_sync(0xffffffffu, mm > thresh)) {
            lse_update(m, s, x0);
            lse_update(m, s, x1);
            lse_update(m, s, x2);
            lse_update(m, s, x3);
        }
    }
#pragma unroll
    for (int off = 16; off; off >>= 1) {
        float mo = __shfl_xor_sync(0xffffffffu, m, off);
        float so = __shfl_xor_sync(0xffffffffu, s, off);
        lse_merge(m, s, mo, so);
    }
    if (lane == 0) g_lu[i] = -12.0f - (m + log2f(s));
}

// Col pass: lv2_j = -12 - log2sum_i 2^(mK2_ij + lu2_i). Lane-per-column, 8 warps split rows.
__global__ void col_pass()
{
    __shared__ float smn[8][33];
    __shared__ float ssm[8][33];
    int warp = threadIdx.x >> 5, lane = threadIdx.x & 31;
    int c = blockIdx.x * 32 + lane;
    float m_init = fmaf(NEGK2, g_colmin[c], g_lu[g_colarg[c]]);
    float thresh = m_init - TH;
    float m = m_init, s = 0.f;
    int rbase = warp * 512;
    for (int rr = 0; rr < 512; rr += 8) {
        float x[8];
        float mm = -3.0e38f;
#pragma unroll
        for (int k = 0; k < 8; k++) {
            float cc = g_cost[(size_t)(rbase + rr + k) * NB + c];
            x[k] = fmaf(NEGK2, cc, g_lu[rbase + rr + k]);
            mm = fmaxf(mm, x[k]);
        }
        if (__any_sync(0xffffffffu, mm > thresh)) {
#pragma unroll
            for (int k = 0; k < 8; k++) lse_update(m, s, x[k]);
        }
    }
    smn[warp][lane] = m;
    ssm[warp][lane] = s;
    __syncthreads();
    if (warp == 0) {
#pragma unroll
        for (int w = 1; w < 8; w++) lse_merge(m, s, smn[w][lane], ssm[w][lane]);
        g_lv[c] = -12.0f - (m + log2f(s));
    }
}

// ---------------------------------------------------------------- loss = sum pi*cost
__global__ void loss_kernel(float* __restrict__ out)
{
    int warp = threadIdx.x >> 5, lane = threadIdx.x & 31;
    int i = blockIdx.x * 8 + warp;
    float lui = g_lu[i];
    float acc = 0.f;
    const float4* crow = reinterpret_cast<const float4*>(g_cost + (size_t)i * NB);
    const float4* lv4  = reinterpret_cast<const float4*>(g_lv);
#pragma unroll 4
    for (int step = 0; step < NB / 128; step++) {
        int j4 = step * 32 + lane;
        float4 c = crow[j4];
        float4 v = lv4[j4];
        float e0 = lui + fmaf(NEGK2, c.x, v.x);
        float e1 = lui + fmaf(NEGK2, c.y, v.y);
        float e2 = lui + fmaf(NEGK2, c.z, v.z);
        float e3 = lui + fmaf(NEGK2, c.w, v.w);
        float mm = fmaxf(fmaxf(e0, e1), fmaxf(e2, e3));
        if (__any_sync(0xffffffffu, mm > -ETH)) {
            acc += exp2f(e0) * c.x + exp2f(e1) * c.y + exp2f(e2) * c.z + exp2f(e3) * c.w;
        }
    }
#pragma unroll
    for (int off = 16; off; off >>= 1)
        acc += __shfl_xor_sync(0xffffffffu, acc, off);
    if (lane == 0) atomicAdd(out, acc);
}

// ---------------------------------------------------------------- launch
extern "C" void kernel_launch(void* const* d_in, const int* in_sizes, int n_in,
                              void* d_out, int out_size)
{
    (void)in_sizes; (void)n_in; (void)out_size;
    const float* feat  = (const float*)d_in[0];
    const float* zfeat = (const float*)d_in[1];
    const float* text  = (const float*)d_in[2];
    const float* ztext = (const float*)d_in[3];
    const int*   gt    = (const int*)d_in[4];
    float* out = (float*)d_out;

    build_fz<<<(NB * DD + 255) / 256, 256>>>(feat, zfeat, text, ztext, gt, out);
    sumsq_init<<<NB / 8, 256>>>();
    dim3 grid(32, 32);
    gemm_cost<<<grid, 256>>>();
    rowmin_kernel<<<NB / 8, 256>>>();
    colmin_kernel<<<NB / 32, 256>>>();
    for (int it = 0; it < 50; it++) {
        row_pass<<<NB / 8, 256>>>();
        col_pass<<<NB / 32, 256>>>();
    }
    loss_kernel<<<NB / 8, 256>>>(out);
}

// round 3
// speedup vs baseline: 1.4264x; 1.4264x over previous
#include <cuda_runtime.h>
#include <cuda_bf16.h>
#include <math.h>
#include <stdint.h>

// miniBatchOT: B=4096, concat dim 1024.
// cost[i][j] = max(0, 0.5*||f_i - z_j||^2);  Sinkhorn eps=0.05, 50 iters; out = sum(pi*cost).
// Base-2 Sinkhorn: mK2 = NEGK2*cost, lu2/lv2 duals.
// GEMM: mma.sync bf16x3 (compute_100-safe; tcgen05 not available at this PTX target).

#define NB 4096
#define DD 1024
#define NEGK2 (-28.853900817779268f)   /* -log2(e)/eps */
#define TH    96.0f

// ------------------------------------------------------------------ globals
static __device__ __align__(16) float g_f[NB * DD];
static __device__ __align__(16) float g_z[NB * DD];
static __device__ __align__(16) __nv_bfloat16 g_fh[NB * DD];
static __device__ __align__(16) __nv_bfloat16 g_fl[NB * DD];
static __device__ __align__(16) __nv_bfloat16 g_zh[NB * DD];
static __device__ __align__(16) __nv_bfloat16 g_zl[NB * DD];
static __device__ __align__(16) float g_x2[NB];
static __device__ __align__(16) float g_y2[NB];
static __device__ __align__(16) float g_cost[(size_t)NB * NB];
static __device__ __align__(16) float g_lu[NB];
static __device__ __align__(16) float g_lv[NB];
static __device__ float g_rowmin[NB];
static __device__ int   g_rowarg[NB];
static __device__ float g_colmin[NB];
static __device__ int   g_colarg[NB];
static __device__ unsigned int g_bar_count;
static __device__ unsigned int g_bar_phase;

// ------------------------------------------------------------------ asm helpers
__device__ __forceinline__ uint32_t smem_u32(const void* p) {
    uint32_t a;
    asm("{ .reg .u64 t; cvta.to.shared.u64 t, %1; cvt.u32.u64 %0, t; }" : "=r"(a) : "l"(p));
    return a;
}
#define CP_ASYNC16(dst, src) \
    asm volatile("cp.async.cg.shared.global [%0], [%1], 16;" :: "r"(dst), "l"(src))
#define CP_COMMIT() asm volatile("cp.async.commit_group;")
#define CP_WAIT(n)  asm volatile("cp.async.wait_group %0;" :: "n"(n))

#define LDMX4(r0, r1, r2, r3, addr) \
    asm volatile("ldmatrix.sync.aligned.m8n8.x4.shared.b16 {%0,%1,%2,%3}, [%4];" \
                 : "=r"(r0), "=r"(r1), "=r"(r2), "=r"(r3) : "r"(addr))

#define MMA16816(d, a, b0v, b1v) \
    asm volatile("mma.sync.aligned.m16n8k16.row.col.f32.bf16.bf16.f32 " \
                 "{%0,%1,%2,%3}, {%4,%5,%6,%7}, {%8,%9}, {%0,%1,%2,%3};" \
                 : "+f"((d)[0]), "+f"((d)[1]), "+f"((d)[2]), "+f"((d)[3]) \
                 : "r"((a)[0]), "r"((a)[1]), "r"((a)[2]), "r"((a)[3]), "r"(b0v), "r"(b1v))

// lse helpers (base-2)
__device__ __forceinline__ void lse_update(float& m, float& s, float x) {
    if (x <= m) s += exp2f(x - m);
    else { s = fmaf(s, exp2f(m - x), 1.0f); m = x; }
}
__device__ __forceinline__ void lse_merge(float& m, float& s, float mo, float so) {
    float M = fmaxf(m, mo);
    s = s * exp2f(m - M) + so * exp2f(mo - M);
    m = M;
}

// ------------------------------------------------------------------ build f,z (+ bf16 hi/lo split)
__global__ void build_fz(const float* __restrict__ feat,
                         const float* __restrict__ zfeat,
                         const float* __restrict__ text,
                         const float* __restrict__ ztext,
                         const int*   __restrict__ gt,
                         float* __restrict__ out)
{
    int idx = blockIdx.x * blockDim.x + threadIdx.x;
    if (idx == 0) { out[0] = 0.0f; g_bar_count = 0u; g_bar_phase = 0u; }
    if (idx >= NB * DD) return;
    int i = idx >> 10;
    int d = idx & 1023;
    int g = gt[i];
    float fv, zv;
    if (d < 512) {
        fv = feat[i * 512 + d];
        zv = zfeat[i * 512 + d];
    } else {
        int dd = d - 512;
        fv = text[g * 512 + dd];
        zv = ztext[g * 512 + dd];
    }
    g_f[idx] = fv;
    g_z[idx] = zv;
    __nv_bfloat16 fh = __float2bfloat16(fv);
    __nv_bfloat16 zh = __float2bfloat16(zv);
    g_fh[idx] = fh;
    g_zh[idx] = zh;
    g_fl[idx] = __float2bfloat16(fv - __bfloat162float(fh));
    g_zl[idx] = __float2bfloat16(zv - __bfloat162float(zh));
}

// ------------------------------------------------------------------ row norms + dual init
__global__ void sumsq_init()
{
    int warp = threadIdx.x >> 5, lane = threadIdx.x & 31;
    int i = blockIdx.x * 8 + warp;
    const float4* f4 = reinterpret_cast<const float4*>(g_f + (size_t)i * DD);
    const float4* z4 = reinterpret_cast<const float4*>(g_z + (size_t)i * DD);
    float sx = 0.f, sz = 0.f;
    for (int j = lane; j < DD / 4; j += 32) {
        float4 a = f4[j];
        float4 b = z4[j];
        sx += a.x * a.x + a.y * a.y + a.z * a.z + a.w * a.w;
        sz += b.x * b.x + b.y * b.y + b.z * b.z + b.w * b.w;
    }
#pragma unroll
    for (int off = 16; off; off >>= 1) {
        sx += __shfl_xor_sync(0xffffffffu, sx, off);
        sz += __shfl_xor_sync(0xffffffffu, sz, off);
    }
    if (lane == 0) {
        g_x2[i] = sx;
        g_y2[i] = sz;
        g_lu[i] = 0.f;
        g_lv[i] = 0.f;
    }
}

// ------------------------------------------------------------------ mma.sync cost GEMM (bf16x3)
// Block tile 128x128, K chunks of 32, 8 warps (4 along M x 2 along N), warp tile 32x64.
// smem: 4 arrays (Ah, Al, Bh, Bl) x 128 rows x 32 bf16, rows padded to 80B (conflict-free),
// double-buffered via cp.async.
#define KC 32
#define NCHUNK (DD / KC)              /* 32 */
#define ROWB 80                        /* padded row bytes (32 bf16 = 64B data) */
#define ARRB (128 * ROWB)              /* 10240 */
#define BUFB (4 * ARRB)                /* 40960 */
#define SMEM_G (2 * BUFB)              /* 81920 */

__global__ __launch_bounds__(256, 1)
void gemm_cost_mma()
{
    extern __shared__ char smem[];
    const uint32_t sbase = smem_u32(smem);
    const int tid  = threadIdx.x;
    const int wid  = tid >> 5;
    const int lane = tid & 31;
    const int warp_m = wid & 3;        // 0..3  -> rows warp_m*32
    const int warp_n = wid >> 2;       // 0..1  -> cols warp_n*64
    const int rowBase = blockIdx.y * 128;
    const int colBase = blockIdx.x * 128;

    const __nv_bfloat16* gsrc[4] = { g_fh + (size_t)rowBase * DD,
                                     g_fl + (size_t)rowBase * DD,
                                     g_zh + (size_t)colBase * DD,
                                     g_zl + (size_t)colBase * DD };

    // per-thread copy slots: 8 x 16B; u = tid + i*256 over [arr(4)][row(128)][seg(4)]
    int cp_arr[8], cp_row[8], cp_seg[8];
#pragma unroll
    for (int i = 0; i < 8; i++) {
        int u = tid + i * 256;
        cp_arr[i] = u >> 9;
        cp_row[i] = (u >> 2) & 127;
        cp_seg[i] = u & 3;
    }

    float acc[2][8][4];
#pragma unroll
    for (int mt = 0; mt < 2; mt++)
#pragma unroll
        for (int nt = 0; nt < 8; nt++)
#pragma unroll
            for (int k = 0; k < 4; k++) acc[mt][nt][k] = 0.f;

    // ldmatrix per-lane base offsets
    // A (16x16 x4): row = mtbase + (L&7) + ((L>>3)&1)*8 ; khalf = L>>4
    const uint32_t a_row = (uint32_t)(warp_m * 32 + (lane & 7) + ((lane >> 3) & 1) * 8);
    const uint32_t a_kh  = (uint32_t)(lane >> 4);
    // B (4 ntiles x4): n = nbase + (L>>3)*8 + (L&7) ; khalf fixed per call
    const uint32_t b_row = (uint32_t)(warp_n * 64 + (lane >> 3) * 8 + (lane & 7));

    // prologue: chunk 0 -> buf 0
#pragma unroll
    for (int i = 0; i < 8; i++) {
        const __nv_bfloat16* src = gsrc[cp_arr[i]] + (size_t)cp_row[i] * DD + cp_seg[i] * 8;
        uint32_t dst = sbase + (uint32_t)(cp_arr[i] * ARRB + cp_row[i] * ROWB + cp_seg[i] * 16);
        CP_ASYNC16(dst, src);
    }
    CP_COMMIT();

    for (int c = 0; c < NCHUNK; c++) {
        const int buf = c & 1;
        if (c + 1 < NCHUNK) {
            const uint32_t bb = sbase + (uint32_t)(((c + 1) & 1) * BUFB);
            const int koff = (c + 1) * KC;
#pragma unroll
            for (int i = 0; i < 8; i++) {
                const __nv_bfloat16* src = gsrc[cp_arr[i]] + (size_t)cp_row[i] * DD + koff + cp_seg[i] * 8;
                uint32_t dst = bb + (uint32_t)(cp_arr[i] * ARRB + cp_row[i] * ROWB + cp_seg[i] * 16);
                CP_ASYNC16(dst, src);
            }
            CP_COMMIT();
            CP_WAIT(1);
        } else {
            CP_WAIT(0);
        }
        __syncthreads();

        const uint32_t bb = sbase + (uint32_t)(buf * BUFB);
        const uint32_t baseAh = bb;
        const uint32_t baseAl = bb + ARRB;
        const uint32_t baseBh = bb + 2 * ARRB;
        const uint32_t baseBl = bb + 3 * ARRB;

#pragma unroll
        for (int ks = 0; ks < 2; ks++) {
            uint32_t ah[2][4], al[2][4];
            uint32_t bh[8][2], bl[8][2];
            const uint32_t aseg = (uint32_t)(ks * 2) + a_kh;
#pragma unroll
            for (int mt = 0; mt < 2; mt++) {
                uint32_t aoff = (a_row + mt * 16) * ROWB + aseg * 16;
                LDMX4(ah[mt][0], ah[mt][1], ah[mt][2], ah[mt][3], baseAh + aoff);
                LDMX4(al[mt][0], al[mt][1], al[mt][2], al[mt][3], baseAl + aoff);
            }
#pragma unroll
            for (int bg = 0; bg < 2; bg++) {
                uint32_t boff0 = (b_row + bg * 32) * ROWB + (uint32_t)(ks * 2) * 16;
                uint32_t boff1 = boff0 + 16;
                uint32_t t0, t1, t2, t3;
                LDMX4(t0, t1, t2, t3, baseBh + boff0);
                bh[bg * 4 + 0][0] = t0; bh[bg * 4 + 1][0] = t1;
                bh[bg * 4 + 2][0] = t2; bh[bg * 4 + 3][0] = t3;
                LDMX4(t0, t1, t2, t3, baseBh + boff1);
                bh[bg * 4 + 0][1] = t0; bh[bg * 4 + 1][1] = t1;
                bh[bg * 4 + 2][1] = t2; bh[bg * 4 + 3][1] = t3;
                LDMX4(t0, t1, t2, t3, baseBl + boff0);
                bl[bg * 4 + 0][0] = t0; bl[bg * 4 + 1][0] = t1;
                bl[bg * 4 + 2][0] = t2; bl[bg * 4 + 3][0] = t3;
                LDMX4(t0, t1, t2, t3, baseBl + boff1);
                bl[bg * 4 + 0][1] = t0; bl[bg * 4 + 1][1] = t1;
                bl[bg * 4 + 2][1] = t2; bl[bg * 4 + 3][1] = t3;
            }
#pragma unroll
            for (int mt = 0; mt < 2; mt++)
#pragma unroll
                for (int nt = 0; nt < 8; nt++) {
                    MMA16816(acc[mt][nt], ah[mt], bh[nt][0], bh[nt][1]);
                    MMA16816(acc[mt][nt], ah[mt], bl[nt][0], bl[nt][1]);
                    MMA16816(acc[mt][nt], al[mt], bh[nt][0], bh[nt][1]);
                }
        }
        __syncthreads();
    }

    // epilogue: cost = max(0, 0.5*x2_i + 0.5*y2_j - dot)
    const int r  = lane >> 2;
    const int c2 = (lane & 3) * 2;
#pragma unroll
    for (int mt = 0; mt < 2; mt++) {
        int i0 = rowBase + warp_m * 32 + mt * 16 + r;
        float hx0 = 0.5f * g_x2[i0];
        float hx1 = 0.5f * g_x2[i0 + 8];
        float* row0 = g_cost + (size_t)i0 * NB + colBase + warp_n * 64;
        float* row1 = row0 + (size_t)8 * NB;
#pragma unroll
        for (int nt = 0; nt < 8; nt++) {
            int j = warp_n * 64 + nt * 8 + c2;
            float hy0 = 0.5f * g_y2[colBase + j];
            float hy1 = 0.5f * g_y2[colBase + j + 1];
            float2 o0, o1;
            o0.x = fmaxf(0.f, hx0 + hy0 - acc[mt][nt][0]);
            o0.y = fmaxf(0.f, hx0 + hy1 - acc[mt][nt][1]);
            o1.x = fmaxf(0.f, hx1 + hy0 - acc[mt][nt][2]);
            o1.y = fmaxf(0.f, hx1 + hy1 - acc[mt][nt][3]);
            *reinterpret_cast<float2*>(row0 + nt * 8 + c2) = o0;
            *reinterpret_cast<float2*>(row1 + nt * 8 + c2) = o1;
        }
    }
}

// ------------------------------------------------------------------ persistent Sinkhorn
__device__ __forceinline__ void grid_sync_(unsigned int* myphase, int nblocks)
{
    __threadfence();
    __syncthreads();
    if (threadIdx.x == 0) {
        unsigned int arrived = atomicAdd(&g_bar_count, 1u);
        if (arrived == (unsigned int)(nblocks - 1)) {
            atomicExch(&g_bar_count, 0u);
            __threadfence();
            atomicAdd(&g_bar_phase, 1u);
        } else {
            volatile unsigned int* vp = &g_bar_phase;
            while (*vp == *myphase) { __nanosleep(64); }
        }
    }
    __syncthreads();
    (*myphase)++;
}

__global__ __launch_bounds__(1024, 1)
void sinkhorn_persist(float* __restrict__ out, int nblocks)
{
    __shared__ float sm_m[32][33];
    __shared__ float sm_s[32][33];
    __shared__ int   sm_a[32][33];

    const int tid  = threadIdx.x;
    const int warp = tid >> 5;
    const int lane = tid & 31;
    const int gwarp = blockIdx.x * 32 + warp;
    const int totwarps = nblocks * 32;
    unsigned int phase = 0;

    // ---- seeds: rowmin (warp per row) and colmin (block per 32-col tile)
    for (int row = gwarp; row < NB; row += totwarps) {
        const float4* crow = reinterpret_cast<const float4*>(g_cost + (size_t)row * NB);
        float mn = 3.4e38f; int arg = 0;
        for (int j4 = lane; j4 < NB / 4; j4 += 32) {
            float4 cc = crow[j4];
            int j = j4 * 4;
            if (cc.x < mn) { mn = cc.x; arg = j; }
            if (cc.y < mn) { mn = cc.y; arg = j + 1; }
            if (cc.z < mn) { mn = cc.z; arg = j + 2; }
            if (cc.w < mn) { mn = cc.w; arg = j + 3; }
        }
#pragma unroll
        for (int off = 16; off; off >>= 1) {
            float mo = __shfl_xor_sync(0xffffffffu, mn, off);
            int   ao = __shfl_xor_sync(0xffffffffu, arg, off);
            if (mo < mn) { mn = mo; arg = ao; }
        }
        if (lane == 0) { g_rowmin[row] = mn; g_rowarg[row] = arg; }
    }
    for (int t = blockIdx.x; t < NB / 32; t += nblocks) {
        int c = t * 32 + lane;
        int rbase = warp * 128;
        float mn = 3.4e38f; int arg = 0;
        for (int rr = 0; rr < 128; rr++) {
            float v = g_cost[(size_t)(rbase + rr) * NB + c];
            if (v < mn) { mn = v; arg = rbase + rr; }
        }
        sm_m[warp][lane] = mn;
        sm_a[warp][lane] = arg;
        __syncthreads();
        if (warp == 0) {
#pragma unroll
            for (int w = 1; w < 32; w++) {
                if (sm_m[w][lane] < mn) { mn = sm_m[w][lane]; arg = sm_a[w][lane]; }
            }
            g_colmin[c] = mn;
            g_colarg[c] = arg;
        }
        __syncthreads();
    }
    grid_sync_(&phase, nblocks);

    // ---- 50 Sinkhorn iterations
    for (int it = 0; it < 50; it++) {
        // row pass: lu = -12 - lse_j(NEGK2*cost + lv_j)
        for (int row = gwarp; row < NB; row += totwarps) {
            float m_init = fmaf(NEGK2, __ldcg(&g_rowmin[row]), __ldcg(&g_lv[__ldcg(&g_rowarg[row])]));
            float thresh = m_init - TH;
            float m = m_init, s = 0.f;
            const float4* crow = reinterpret_cast<const float4*>(g_cost + (size_t)row * NB);
            const float4* lv4  = reinterpret_cast<const float4*>(g_lv);
#pragma unroll 4
            for (int step = 0; step < NB / 128; step++) {
                int j4 = step * 32 + lane;
                float4 cc = crow[j4];
                float4 v  = __ldcg(lv4 + j4);
                float x0 = fmaf(NEGK2, cc.x, v.x);
                float x1 = fmaf(NEGK2, cc.y, v.y);
                float x2 = fmaf(NEGK2, cc.z, v.z);
                float x3 = fmaf(NEGK2, cc.w, v.w);
                float mm = fmaxf(fmaxf(x0, x1), fmaxf(x2, x3));
                if (__any_sync(0xffffffffu, mm > thresh)) {
                    lse_update(m, s, x0);
                    lse_update(m, s, x1);
                    lse_update(m, s, x2);
                    lse_update(m, s, x3);
                }
            }
#pragma unroll
            for (int off = 16; off; off >>= 1) {
                float mo = __shfl_xor_sync(0xffffffffu, m, off);
                float so = __shfl_xor_sync(0xffffffffu, s, off);
                lse_merge(m, s, mo, so);
            }
            if (lane == 0) g_lu[row] = -12.0f - (m + log2f(s));
        }
        grid_sync_(&phase, nblocks);

        // col pass: lv = -12 - lse_i(NEGK2*cost + lu_i)
        for (int t = blockIdx.x; t < NB / 32; t += nblocks) {
            int c = t * 32 + lane;
            float m_init = fmaf(NEGK2, __ldcg(&g_colmin[c]), __ldcg(&g_lu[__ldcg(&g_colarg[c])]));
            float thresh = m_init - TH;
            float m = m_init, s = 0.f;
            int rbase = warp * 128;
            for (int rr = 0; rr < 128; rr += 8) {
                float x[8];
                float mm = -3.0e38f;
#pragma unroll
                for (int k = 0; k < 8; k++) {
                    float cc = g_cost[(size_t)(rbase + rr + k) * NB + c];
                    float lu_k = __ldcg(&g_lu[rbase + rr + k]);
                    x[k] = fmaf(NEGK2, cc, lu_k);
                    mm = fmaxf(mm, x[k]);
                }
                if (__any_sync(0xffffffffu, mm > thresh)) {
#pragma unroll
                    for (int k = 0; k < 8; k++) lse_update(m, s, x[k]);
                }
            }
            sm_m[warp][lane] = m;
            sm_s[warp][lane] = s;
            __syncthreads();
            if (warp == 0) {
#pragma unroll
                for (int w = 1; w < 32; w++) lse_merge(m, s, sm_m[w][lane], sm_s[w][lane]);
                g_lv[c] = -12.0f - (m + log2f(s));
            }
            __syncthreads();
        }
        grid_sync_(&phase, nblocks);
    }

    // ---- loss = sum pi * cost
    float acc = 0.f;
    for (int row = gwarp; row < NB; row += totwarps) {
        float lui = __ldcg(&g_lu[row]);
        const float4* crow = reinterpret_cast<const float4*>(g_cost + (size_t)row * NB);
        const float4* lv4  = reinterpret_cast<const float4*>(g_lv);
#pragma unroll 4
        for (int step = 0; step < NB / 128; step++) {
            int j4 = step * 32 + lane;
            float4 cc = crow[j4];
            float4 v  = __ldcg(lv4 + j4);
            float e0 = lui + fmaf(NEGK2, cc.x, v.x);
            float e1 = lui + fmaf(NEGK2, cc.y, v.y);
            float e2 = lui + fmaf(NEGK2, cc.z, v.z);
            float e3 = lui + fmaf(NEGK2, cc.w, v.w);
            float mm = fmaxf(fmaxf(e0, e1), fmaxf(e2, e3));
            if (__any_sync(0xffffffffu, mm > -60.0f)) {
                acc += exp2f(e0) * cc.x + exp2f(e1) * cc.y + exp2f(e2) * cc.z + exp2f(e3) * cc.w;
            }
        }
    }
#pragma unroll
    for (int off = 16; off; off >>= 1)
        acc += __shfl_xor_sync(0xffffffffu, acc, off);
    if (lane == 0 && acc != 0.f) atomicAdd(out, acc);
}

// ------------------------------------------------------------------ launch
extern "C" void kernel_launch(void* const* d_in, const int* in_sizes, int n_in,
                              void* d_out, int out_size)
{
    (void)in_sizes; (void)n_in; (void)out_size;
    const float* feat  = (const float*)d_in[0];
    const float* zfeat = (const float*)d_in[1];
    const float* text  = (const float*)d_in[2];
    const float* ztext = (const float*)d_in[3];
    const int*   gt    = (const int*)d_in[4];
    float* out = (float*)d_out;

    int nsm = 0;
    cudaDeviceGetAttribute(&nsm, cudaDevAttrMultiProcessorCount, 0);
    if (nsm <= 0) nsm = 148;

    build_fz<<<(NB * DD + 255) / 256, 256>>>(feat, zfeat, text, ztext, gt, out);
    sumsq_init<<<NB / 8, 256>>>();

    cudaFuncSetAttribute(gemm_cost_mma, cudaFuncAttributeMaxDynamicSharedMemorySize, SMEM_G);
    dim3 grid(NB / 128, NB / 128);
    gemm_cost_mma<<<grid, 256, SMEM_G>>>();

    sinkhorn_persist<<<nsm, 1024>>>(out, nsm);
}